// round 14
// baseline (speedup 1.0000x reference)
#include <cuda_runtime.h>
#include <cstdint>

#define DIM   1024
#define NSLOT 32
#define NTOK  2048
#define NQ    32768
#define BS    64
#define NBLK  32
#define FULLM 0xffffffffu
#define INV_TEMP (1.0f/0.35f)

typedef unsigned long long u64;

// ---- device scratch ----
__device__ __align__(16) float g_G[NTOK * (size_t)NTOK];   // Gram, upper triangle valid
__device__ __align__(16) float g_D[NSLOT * NTOK];          // slot-token dots
__device__ int   g_jl[NTOK];
__device__ __align__(16) float g_slots[NSLOT * DIM];
__device__ float g_invn[NSLOT];

// ---- packed f32x2 helpers ----
__device__ __forceinline__ void ffma2(u64 &d, u64 a, u64 b) {
  asm("fma.rn.f32x2 %0, %1, %2, %0;" : "+l"(d) : "l"(a), "l"(b));
}
__device__ __forceinline__ u64 mul2(u64 a, u64 b) {
  u64 d; asm("mul.rn.f32x2 %0, %1, %2;" : "=l"(d) : "l"(a), "l"(b)); return d;
}
__device__ __forceinline__ u64 pack2(float x) {
  u64 d; asm("mov.b64 %0, {%1, %1};" : "=l"(d) : "f"(x)); return d;
}
__device__ __forceinline__ float hsum2(u64 u) {
  float lo, hi; asm("mov.b64 {%0, %1}, %2;" : "=f"(lo), "=f"(hi) : "l"(u));
  return lo + hi;
}

// ---------------------------------------------------------------------------
// Gram GEMM: triangular tile grid (136 CTAs), FFMA2 microkernel, 2-stage
// smem double-buffer: LDG(ch+1) issues BEFORE compute(ch), STS lands after.
// One barrier per chunk. Accumulation order identical to R10 -> same G bits.
// ---------------------------------------------------------------------------
__global__ __launch_bounds__(256, 2) void gram_kernel(const float* __restrict__ W) {
  int ttile = blockIdx.x, bx = 0;
  while (ttile >= 16 - bx) { ttile -= 16 - bx; bx++; }
  const int by = bx + ttile;

  __shared__ float As[2][16][132];
  __shared__ float Bs[2][16][132];
  const int tid = threadIdx.x;
  const int tx = tid & 15, ty = tid >> 4;
  u64 acc2[8][4];
#pragma unroll
  for (int m = 0; m < 8; m++)
#pragma unroll
    for (int p = 0; p < 4; p++) acc2[m][p] = 0ull;
  const int r0 = bx * 128, c0 = by * 128;
  const int lr = tid >> 2, kq = (tid & 3) << 2;

  const float* pa0 = &W[(size_t)(r0 + lr) * DIM + kq];
  const float* pa1 = &W[(size_t)(r0 + lr + 64) * DIM + kq];
  const float* pb0 = &W[(size_t)(c0 + lr) * DIM + kq];
  const float* pb1 = &W[(size_t)(c0 + lr + 64) * DIM + kq];

  // prologue: chunk 0 -> stage 0
  float4 a0 = *(const float4*)pa0;
  float4 a1 = *(const float4*)pa1;
  float4 b0 = *(const float4*)pb0;
  float4 b1 = *(const float4*)pb1;
  As[0][kq + 0][lr] = a0.x; As[0][kq + 1][lr] = a0.y; As[0][kq + 2][lr] = a0.z; As[0][kq + 3][lr] = a0.w;
  As[0][kq + 0][lr + 64] = a1.x; As[0][kq + 1][lr + 64] = a1.y; As[0][kq + 2][lr + 64] = a1.z; As[0][kq + 3][lr + 64] = a1.w;
  Bs[0][kq + 0][lr] = b0.x; Bs[0][kq + 1][lr] = b0.y; Bs[0][kq + 2][lr] = b0.z; Bs[0][kq + 3][lr] = b0.w;
  Bs[0][kq + 0][lr + 64] = b1.x; Bs[0][kq + 1][lr + 64] = b1.y; Bs[0][kq + 2][lr + 64] = b1.z; Bs[0][kq + 3][lr + 64] = b1.w;
  __syncthreads();

  for (int ch = 0; ch < 64; ch++) {
    const int st = ch & 1;
    const bool more = (ch + 1 < 64);
    if (more) {                               // loads issue BEFORE compute
      const int k1 = (ch + 1) * 16;
      a0 = *(const float4*)(pa0 + k1);
      a1 = *(const float4*)(pa1 + k1);
      b0 = *(const float4*)(pb0 + k1);
      b1 = *(const float4*)(pb1 + k1);
    }
#pragma unroll
    for (int kk = 0; kk < 16; kk++) {
      float a[8];
      *(float4*)a       = *(const float4*)&As[st][kk][ty * 8];
      *(float4*)(a + 4) = *(const float4*)&As[st][kk][ty * 8 + 4];
      u64 b2[4];
      *(ulonglong2*)&b2[0] = *(const ulonglong2*)&Bs[st][kk][tx * 8];
      *(ulonglong2*)&b2[2] = *(const ulonglong2*)&Bs[st][kk][tx * 8 + 4];
#pragma unroll
      for (int m = 0; m < 8; m++) {
        const u64 am = pack2(a[m]);
#pragma unroll
        for (int p = 0; p < 4; p++) ffma2(acc2[m][p], am, b2[p]);
      }
    }
    if (more) {                               // latency hidden by compute above
      const int sn = st ^ 1;
      As[sn][kq + 0][lr] = a0.x; As[sn][kq + 1][lr] = a0.y; As[sn][kq + 2][lr] = a0.z; As[sn][kq + 3][lr] = a0.w;
      As[sn][kq + 0][lr + 64] = a1.x; As[sn][kq + 1][lr + 64] = a1.y; As[sn][kq + 2][lr + 64] = a1.z; As[sn][kq + 3][lr + 64] = a1.w;
      Bs[sn][kq + 0][lr] = b0.x; Bs[sn][kq + 1][lr] = b0.y; Bs[sn][kq + 2][lr] = b0.z; Bs[sn][kq + 3][lr] = b0.w;
      Bs[sn][kq + 0][lr + 64] = b1.x; Bs[sn][kq + 1][lr + 64] = b1.y; Bs[sn][kq + 2][lr + 64] = b1.z; Bs[sn][kq + 3][lr + 64] = b1.w;
    }
    __syncthreads();
  }

  const int rr = r0 + ty * 8, cc2 = c0 + tx * 8;
#pragma unroll
  for (int m = 0; m < 8; m++) {
    ulonglong2 v0, v1;
    v0.x = acc2[m][0]; v0.y = acc2[m][1];
    v1.x = acc2[m][2]; v1.y = acc2[m][3];
    *(ulonglong2*)&g_G[(size_t)(rr + m) * NTOK + cc2]     = v0;
    *(ulonglong2*)&g_G[(size_t)(rr + m) * NTOK + cc2 + 4] = v1;
  }
}

// ---------------------------------------------------------------------------
// prep: D0[j][k] = slots_in[j] . t_k. Warp per column, slots cached in smem.
// ---------------------------------------------------------------------------
__global__ __launch_bounds__(512, 1) void prep_d0(
    const float* __restrict__ W, const float* __restrict__ slots_in) {
  extern __shared__ __align__(16) float sm[];
  const int tid = threadIdx.x, l = tid & 31, w = tid >> 5;
  {
    float4* d4 = (float4*)sm;
    const float4* s4 = (const float4*)slots_in;
    for (int k = tid; k < NSLOT * DIM / 4; k += 512) d4[k] = s4[k];
  }
  __syncthreads();
  const ulonglong2* sm2 = (const ulonglong2*)sm;
  const int k = blockIdx.x * 16 + w;
  const ulonglong2* xp = (const ulonglong2*)(W + (size_t)k * DIM);
  u64 xv[16];
#pragma unroll
  for (int q = 0; q < 8; q++) {
    ulonglong2 v = xp[l + 32 * q];
    xv[2 * q] = v.x; xv[2 * q + 1] = v.y;
  }
  float v[NSLOT];
#pragma unroll
  for (int j = 0; j < NSLOT; j++) {
    u64 p0 = 0, p1 = 0;
#pragma unroll
    for (int q = 0; q < 8; q++) {
      ulonglong2 sv = sm2[j * 256 + l + 32 * q];
      ffma2(p0, sv.x, xv[2 * q]); ffma2(p1, sv.y, xv[2 * q + 1]);
    }
    v[j] = hsum2(p0) + hsum2(p1);
  }
#pragma unroll
  for (int o = 16; o; o >>= 1) {
    bool hi = (l & o) != 0;
#pragma unroll
    for (int j = 0; j < o; j++) {
      float snd = hi ? v[j] : v[j + o];
      float rcv = __shfl_xor_sync(FULLM, snd, o);
      v[j] = (hi ? v[j + o] : v[j]) + rcv;
    }
  }
  g_D[l * NTOK + k] = v[0];
}

// ---------------------------------------------------------------------------
// Scan: 1 CTA x 768 threads (unchanged from R10).
// ---------------------------------------------------------------------------
struct ScanSmem {
  float t2s[NTOK];
  float Dcol[2][BS][33];
  float Gdiag[2][BS][BS];
  float Gcross[BS][65];
  float pow95[BS + 1];
  float cvec[2][NSLOT];
  float swW[2][BS];
  float n2sh[NSLOT];
  int   sstart[2][NSLOT + 1];
  int   jlistS[2][BS];
  int   ordS[2][BS];
  int   mvec[2][NSLOT];
  int   swS[2][BS];
};

__global__ __launch_bounds__(768, 1) void scan_kernel(
    const float* __restrict__ slots_in, const float* __restrict__ usage_in) {
  extern __shared__ __align__(16) char smraw[];
  ScanSmem* S = (ScanSmem*)smraw;
  const int tid = threadIdx.x, w = tid >> 5, l = tid & 31;

  for (int t = tid; t < NTOK; t += 768) S->t2s[t] = g_G[(size_t)t * NTOK + t];
  for (int t = tid; t < NSLOT * BS; t += 768)
    S->Dcol[0][t & 63][t >> 6] = g_D[(t >> 6) * NTOK + (t & 63)];
  for (int t = tid; t < BS * BS; t += 768)
    S->Gdiag[0][t >> 6][t & 63] = g_G[(size_t)(t >> 6) * NTOK + (t & 63)];
  if (tid == 0) {
    float p = 1.f;
    for (int e = 0; e <= BS; e++) { S->pow95[e] = p; p *= 0.95f; }
  }
  for (int s = w; s < NSLOT; s += 24) {
    const float4* sp = (const float4*)(slots_in + (size_t)s * DIM);
    float a = 0.f;
#pragma unroll
    for (int q = 0; q < 8; q++) {
      float4 v = sp[l + 32 * q];
      a = fmaf(v.x, v.x, fmaf(v.y, v.y, fmaf(v.z, v.z, fmaf(v.w, v.w, a))));
    }
#pragma unroll
    for (int o = 16; o; o >>= 1) a += __shfl_xor_sync(FULLM, a, o);
    if (l == 0) S->n2sh[s] = a;
  }
  __syncthreads();

  float n2 = 0.f, usg = 0.f, rcp = 0.f;
  int nempty = 0;
  if (w == 0) {
    n2 = S->n2sh[l];
    usg = usage_in[l];
    rcp = rsqrtf(fmaxf(n2, 1e-16f));
    nempty = __popc(__ballot_sync(FULLM, usg == 0.f));
  }

  int cur = 0;
  for (int b = 0; b < NBLK; b++) {
    if (w == 0) {
      const int lb = b & 1;
      int mb = 0;
      float dn = S->Dcol[cur][0][l];
      for (int s = 0; s < BS; s++) {
        const int gi = b * BS + s;
        const int sn = (s < BS - 1) ? s + 1 : s;
        const float dnext = S->Dcol[cur][sn][l];
        const float gdn = S->Gdiag[cur][s][sn];
        const float n2c = 0.9025f * n2 + 0.095f * dn + 0.0025f * S->t2s[gi];
        const float rcpc = rsqrtf(fmaxf(n2c, 1e-16f));
        int j;
        if (nempty > 0) {
          unsigned em = __ballot_sync(FULLM, usg == 0.f);
          j = __ffs(em) - 1;
          nempty--;
        } else {
          float sim = dn * rcp;
          unsigned bk = __float_as_uint(sim);
          bk ^= (unsigned)((int)bk >> 31) | 0x80000000u;
          unsigned mk = __reduce_max_sync(FULLM, bk);
          j = __ffs(__ballot_sync(FULLM, bk == mk)) - 1;
        }
        const bool win = (l == j);
        if (win) {
          S->jlistS[lb][s] = j; S->ordS[lb][s] = mb;
          g_jl[gi] = j;
          n2 = n2c; rcp = rcpc;
          usg += 1.f; mb++;
        }
        dn = win ? fmaf(0.95f, dnext, 0.05f * gdn) : dnext;
        const int r1 = s + 2 + l;
        if (r1 < BS)
          S->Dcol[cur][r1][j] = fmaf(0.95f, S->Dcol[cur][r1][j], 0.05f * S->Gdiag[cur][s][r1]);
        const int r2 = s + 34 + l;
        if (r2 < BS)
          S->Dcol[cur][r2][j] = fmaf(0.95f, S->Dcol[cur][r2][j], 0.05f * S->Gdiag[cur][s][r2]);
      }
      S->mvec[lb][l] = mb;
      S->cvec[lb][l] = S->pow95[mb];
      int sc = mb;
#pragma unroll
      for (int o = 1; o < 32; o <<= 1) {
        int v = __shfl_up_sync(FULLM, sc, o);
        if (l >= o) sc += v;
      }
      S->sstart[lb][l] = sc - mb;
      if (l == 31) S->sstart[lb][32] = sc;
      __syncwarp();
      for (int s = l; s < BS; s += 32) {
        int j2 = S->jlistS[lb][s], od = S->ordS[lb][s];
        int pos = S->sstart[lb][j2] + od;
        S->swS[lb][pos] = s;
        S->swW[lb][pos] = 0.05f * S->pow95[S->mvec[lb][j2] - 1 - od];
      }
    } else {
      const int wt = (w - 1) * 32 + l;
      if (b > 0) {
        const int lb = (b - 1) & 1;
        const int j = wt & 31;
        const int g0 = wt >> 5;
        const int colstart = (b + 1) * BS;
        const int ngrp = (NTOK - colstart) >> 2;
        const float c = S->cvec[lb][j];
        const int e0 = S->sstart[lb][j], e1 = S->sstart[lb][j + 1];
        float* const drow = &g_D[j * NTOK];
        int g = g0;
        for (; g + 23 < ngrp; g += 46) {
          const int kqA = colstart + g * 4;
          const int kqB = colstart + (g + 23) * 4;
          float4 dA = *(const float4*)&drow[kqA];
          float4 dB = *(const float4*)&drow[kqB];
          dA.x *= c; dA.y *= c; dA.z *= c; dA.w *= c;
          dB.x *= c; dB.y *= c; dB.z *= c; dB.w *= c;
#pragma unroll 1
          for (int e = e0; e < e1; e++) {
            const int gi = (b - 1) * BS + S->swS[lb][e];
            const float wgt = S->swW[lb][e];
            const float4 gA = *(const float4*)&g_G[(size_t)gi * NTOK + kqA];
            const float4 gB = *(const float4*)&g_G[(size_t)gi * NTOK + kqB];
            dA.x = fmaf(wgt, gA.x, dA.x); dA.y = fmaf(wgt, gA.y, dA.y);
            dA.z = fmaf(wgt, gA.z, dA.z); dA.w = fmaf(wgt, gA.w, dA.w);
            dB.x = fmaf(wgt, gB.x, dB.x); dB.y = fmaf(wgt, gB.y, dB.y);
            dB.z = fmaf(wgt, gB.z, dB.z); dB.w = fmaf(wgt, gB.w, dB.w);
          }
          *(float4*)&drow[kqA] = dA;
          *(float4*)&drow[kqB] = dB;
        }
        for (; g < ngrp; g += 23) {
          const int kq = colstart + g * 4;
          float4 dv = *(const float4*)&drow[kq];
          dv.x *= c; dv.y *= c; dv.z *= c; dv.w *= c;
#pragma unroll 1
          for (int e = e0; e < e1; e++) {
            const int gi = (b - 1) * BS + S->swS[lb][e];
            const float wgt = S->swW[lb][e];
            const float4 gv = *(const float4*)&g_G[(size_t)gi * NTOK + kq];
            dv.x = fmaf(wgt, gv.x, dv.x); dv.y = fmaf(wgt, gv.y, dv.y);
            dv.z = fmaf(wgt, gv.z, dv.z); dv.w = fmaf(wgt, gv.w, dv.w);
          }
          *(float4*)&drow[kq] = dv;
        }
      }
      asm volatile("bar.sync 1, 736;" ::: "memory");
      if (b + 1 < NBLK) {
        const int cb = (b + 1) * BS;
        const int nb2 = cur ^ 1;
        for (int t = wt; t < NSLOT * BS; t += 736)
          S->Dcol[nb2][t & 63][t >> 6] = g_D[(t >> 6) * NTOK + cb + (t & 63)];
        for (int t = wt; t < BS * BS; t += 736)
          S->Gdiag[nb2][t >> 6][t & 63] = g_G[(size_t)(cb + (t >> 6)) * NTOK + cb + (t & 63)];
        for (int t = wt; t < BS * BS; t += 736)
          S->Gcross[t & 63][t >> 6] = g_G[(size_t)(b * BS + (t >> 6)) * NTOK + cb + (t & 63)];
      }
    }
    __syncthreads();
    if (b + 1 < NBLK) {
      const int lb = b & 1;
      const int nb2 = cur ^ 1;
      for (int col = w; col < BS; col += 24) {
        float dvv = S->Dcol[nb2][col][l] * S->cvec[lb][l];
        const int e1 = S->sstart[lb][l + 1];
        for (int e = S->sstart[lb][l]; e < e1; e++)
          dvv = fmaf(S->swW[lb][e], S->Gcross[col][S->swS[lb][e]], dvv);
        S->Dcol[nb2][col][l] = dvv;
      }
    }
    __syncthreads();
    cur ^= 1;
  }
}

// ---------------------------------------------------------------------------
// Recon: prefix-scan per-slot event list, then depth-4 prefetched exact replay.
// ---------------------------------------------------------------------------
__global__ __launch_bounds__(1024, 1) void recon_kernel(
    const float* __restrict__ W, const float* __restrict__ slots_in) {
  __shared__ int jl[NTOK];
  __shared__ int ev[NTOK];
  __shared__ int wsum[32];
  __shared__ float red[32];
  __shared__ int ntot;
  const int j = blockIdx.x, tid = threadIdx.x, l = tid & 31, w = tid >> 5;
  for (int t = tid; t < NTOK; t += 1024) jl[t] = g_jl[t];
  __syncthreads();
  const int m0 = (jl[2 * tid] == j), m1 = (jl[2 * tid + 1] == j);
  const int cnt = m0 + m1;
  int sc = cnt;
#pragma unroll
  for (int o = 1; o < 32; o <<= 1) {
    int v = __shfl_up_sync(FULLM, sc, o);
    if (l >= o) sc += v;
  }
  if (l == 31) wsum[w] = sc;
  __syncthreads();
  if (w == 0) {
    int v = wsum[l];
#pragma unroll
    for (int o = 1; o < 32; o <<= 1) {
      int u = __shfl_up_sync(FULLM, v, o);
      if (l >= o) v += u;
    }
    wsum[l] = v;
    if (l == 31) ntot = v;
  }
  __syncthreads();
  const int base = (w ? wsum[w - 1] : 0) + sc - cnt;
  if (m0) ev[base] = 2 * tid;
  if (m1) ev[base + m0] = 2 * tid + 1;
  __syncthreads();

  const int n = ntot;
  float s = slots_in[(size_t)j * DIM + tid];
  float buf[4];
#pragma unroll
  for (int k = 0; k < 4; k++)
    buf[k] = (k < n) ? W[(size_t)ev[k] * DIM + tid] : 0.f;
  for (int k = 0; k < n; k++) {
    const float wc = buf[k & 3];
    const int kn = k + 4;
    buf[k & 3] = (kn < n) ? W[(size_t)ev[kn] * DIM + tid] : 0.f;
    s = 0.95f * s + 0.05f * wc;
  }
  g_slots[(size_t)j * DIM + tid] = s;
  float ss = s * s;
#pragma unroll
  for (int o = 16; o; o >>= 1) ss += __shfl_xor_sync(FULLM, ss, o);
  if (l == 0) red[w] = ss;
  __syncthreads();
  if (tid < 32) {
    float v = red[tid];
#pragma unroll
    for (int o = 16; o; o >>= 1) v += __shfl_xor_sync(FULLM, v, o);
    if (tid == 0) g_invn[j] = 1.f / fmaxf(sqrtf(fmaxf(v, 0.f)), 1e-12f);
  }
}

// ---------------------------------------------------------------------------
// Retrieve: R3-measured fused kernel (512 threads, 16 warps/SM, 260us).
// ---------------------------------------------------------------------------
__global__ __launch_bounds__(512, 1) void retrieve_kernel(
    const float* __restrict__ x, float* __restrict__ out) {
  extern __shared__ __align__(16) float sm[];
  __shared__ float invn_s[NSLOT];
  const int tid = threadIdx.x, l = tid & 31, w = tid >> 5;

  {
    float4* d4 = (float4*)sm;
    const float4* s4 = (const float4*)g_slots;
    for (int k = tid; k < NSLOT * DIM / 4; k += 512) d4[k] = s4[k];
    if (tid < NSLOT) invn_s[tid] = g_invn[tid];
  }
  __syncthreads();

  const ulonglong2* sm2 = (const ulonglong2*)sm;
  const int gw = blockIdx.x * 16 + w;
  const int nw = gridDim.x * 16;

  for (int t = gw; t < NQ; t += nw) {
    const ulonglong2* xp = (const ulonglong2*)(x + (size_t)t * DIM);
    u64 xv[16];
#pragma unroll
    for (int q = 0; q < 8; q++) {
      ulonglong2 v = xp[l + 32 * q];
      xv[2 * q] = v.x; xv[2 * q + 1] = v.y;
    }
    u64 a = 0, b = 0;
#pragma unroll
    for (int q = 0; q < 8; q++) { ffma2(a, xv[2*q], xv[2*q]); ffma2(b, xv[2*q+1], xv[2*q+1]); }
    float nx = hsum2(a) + hsum2(b);
#pragma unroll
    for (int o = 16; o; o >>= 1) nx += __shfl_xor_sync(FULLM, nx, o);
    float rx = 1.f / fmaxf(sqrtf(nx), 1e-12f);

    float v[NSLOT];
#pragma unroll
    for (int j = 0; j < NSLOT; j++) {
      u64 p0 = 0, p1 = 0;
#pragma unroll
      for (int q = 0; q < 8; q++) {
        ulonglong2 sv = sm2[j * 256 + l + 32 * q];
        ffma2(p0, sv.x, xv[2 * q]); ffma2(p1, sv.y, xv[2 * q + 1]);
      }
      v[j] = hsum2(p0) + hsum2(p1);
    }
#pragma unroll
    for (int o = 16; o; o >>= 1) {
      bool hi = (l & o) != 0;
#pragma unroll
      for (int j = 0; j < o; j++) {
        float snd = hi ? v[j] : v[j + o];
        float rcv = __shfl_xor_sync(FULLM, snd, o);
        v[j] = (hi ? v[j + o] : v[j]) + rcv;
      }
    }
    float sc = v[0] * invn_s[l] * rx * INV_TEMP;
    float m = sc;
#pragma unroll
    for (int o = 16; o; o >>= 1) m = fmaxf(m, __shfl_xor_sync(FULLM, m, o));
    float e = __expf(sc - m);
    float se = e;
#pragma unroll
    for (int o = 16; o; o >>= 1) se += __shfl_xor_sync(FULLM, se, o);
    float r = 1.f / se;

    u64 acc[16];
#pragma unroll
    for (int k = 0; k < 16; k++) acc[k] = 0;
#pragma unroll 8
    for (int j = 0; j < NSLOT; j++) {
      u64 wj = pack2(__shfl_sync(FULLM, e, j));
#pragma unroll
      for (int q = 0; q < 8; q++) {
        ulonglong2 sv = sm2[j * 256 + l + 32 * q];
        ffma2(acc[2 * q], sv.x, wj); ffma2(acc[2 * q + 1], sv.y, wj);
      }
    }
    u64 r2 = pack2(r);
    ulonglong2* op = (ulonglong2*)(out + (size_t)t * DIM);
#pragma unroll
    for (int q = 0; q < 8; q++) {
      ulonglong2 ov; ov.x = mul2(acc[2 * q], r2); ov.y = mul2(acc[2 * q + 1], r2);
      op[l + 32 * q] = ov;
    }
  }
}

extern "C" void kernel_launch(void* const* d_in, const int* in_sizes, int n_in,
                              void* d_out, int out_size) {
  const float* x     = (const float*)d_in[0];
  const float* W     = (const float*)d_in[1];
  const float* slots = (const float*)d_in[2];
  const float* usage = (const float*)d_in[3];
  float* out = (float*)d_out;

  const int slot_smem = NSLOT * DIM * (int)sizeof(float);
  cudaFuncSetAttribute(retrieve_kernel, cudaFuncAttributeMaxDynamicSharedMemorySize, slot_smem);
  cudaFuncSetAttribute(prep_d0, cudaFuncAttributeMaxDynamicSharedMemorySize, slot_smem);
  cudaFuncSetAttribute(scan_kernel, cudaFuncAttributeMaxDynamicSharedMemorySize,
                       (int)sizeof(ScanSmem));

  gram_kernel<<<136, 256>>>(W);
  prep_d0<<<NTOK / 16, 512, slot_smem>>>(W, slots);
  scan_kernel<<<1, 768, sizeof(ScanSmem)>>>(slots, usage);
  recon_kernel<<<NSLOT, 1024>>>(W, slots);
  retrieve_kernel<<<148, 512, slot_smem>>>(x, out);
}

// round 15
// speedup vs baseline: 1.0288x; 1.0288x over previous
#include <cuda_runtime.h>
#include <cstdint>

#define DIM   1024
#define NSLOT 32
#define NTOK  2048
#define NQ    32768
#define BS    64
#define NBLK  32
#define FULLM 0xffffffffu
#define INV_TEMP (1.0f/0.35f)

typedef unsigned long long u64;

// ---- device scratch ----
__device__ __align__(16) float g_G[NTOK * (size_t)NTOK];   // Gram, upper triangle valid
__device__ __align__(16) float g_D[NSLOT * NTOK];          // slot-token dots
__device__ int   g_jl[NTOK];
__device__ __align__(16) float g_slots[NSLOT * DIM];
__device__ float g_invn[NSLOT];
__device__ __align__(16) float g_w[NQ * NSLOT];            // softmax weights

// ---- packed f32x2 helpers ----
__device__ __forceinline__ void ffma2(u64 &d, u64 a, u64 b) {
  asm("fma.rn.f32x2 %0, %1, %2, %0;" : "+l"(d) : "l"(a), "l"(b));
}
__device__ __forceinline__ u64 mul2(u64 a, u64 b) {
  u64 d; asm("mul.rn.f32x2 %0, %1, %2;" : "=l"(d) : "l"(a), "l"(b)); return d;
}
__device__ __forceinline__ u64 pack2(float x) {
  u64 d; asm("mov.b64 %0, {%1, %1};" : "=l"(d) : "f"(x)); return d;
}
__device__ __forceinline__ float hsum2(u64 u) {
  float lo, hi; asm("mov.b64 {%0, %1}, %2;" : "=f"(lo), "=f"(hi) : "l"(u));
  return lo + hi;
}

// ---------------------------------------------------------------------------
// Gram GEMM: triangular tile grid (136 CTAs), FFMA2 microkernel (R10 exact).
// ---------------------------------------------------------------------------
__global__ __launch_bounds__(256, 2) void gram_kernel(const float* __restrict__ W) {
  int ttile = blockIdx.x, bx = 0;
  while (ttile >= 16 - bx) { ttile -= 16 - bx; bx++; }
  const int by = bx + ttile;

  __shared__ float As[16][132];
  __shared__ float Bs[16][132];
  const int tid = threadIdx.x;
  const int tx = tid & 15, ty = tid >> 4;
  u64 acc2[8][4];
#pragma unroll
  for (int m = 0; m < 8; m++)
#pragma unroll
    for (int p = 0; p < 4; p++) acc2[m][p] = 0ull;
  const int r0 = bx * 128, c0 = by * 128;
  const int lr = tid >> 2, kq = (tid & 3) << 2;

  for (int k0 = 0; k0 < DIM; k0 += 16) {
    float4 a0 = *(const float4*)&W[(size_t)(r0 + lr) * DIM + k0 + kq];
    float4 a1 = *(const float4*)&W[(size_t)(r0 + lr + 64) * DIM + k0 + kq];
    float4 b0 = *(const float4*)&W[(size_t)(c0 + lr) * DIM + k0 + kq];
    float4 b1 = *(const float4*)&W[(size_t)(c0 + lr + 64) * DIM + k0 + kq];
    __syncthreads();
    As[kq + 0][lr] = a0.x; As[kq + 1][lr] = a0.y; As[kq + 2][lr] = a0.z; As[kq + 3][lr] = a0.w;
    As[kq + 0][lr + 64] = a1.x; As[kq + 1][lr + 64] = a1.y; As[kq + 2][lr + 64] = a1.z; As[kq + 3][lr + 64] = a1.w;
    Bs[kq + 0][lr] = b0.x; Bs[kq + 1][lr] = b0.y; Bs[kq + 2][lr] = b0.z; Bs[kq + 3][lr] = b0.w;
    Bs[kq + 0][lr + 64] = b1.x; Bs[kq + 1][lr + 64] = b1.y; Bs[kq + 2][lr + 64] = b1.z; Bs[kq + 3][lr + 64] = b1.w;
    __syncthreads();
#pragma unroll
    for (int kk = 0; kk < 16; kk++) {
      float a[8];
      *(float4*)a       = *(const float4*)&As[kk][ty * 8];
      *(float4*)(a + 4) = *(const float4*)&As[kk][ty * 8 + 4];
      u64 b2[4];
      *(ulonglong2*)&b2[0] = *(const ulonglong2*)&Bs[kk][tx * 8];
      *(ulonglong2*)&b2[2] = *(const ulonglong2*)&Bs[kk][tx * 8 + 4];
#pragma unroll
      for (int m = 0; m < 8; m++) {
        const u64 am = pack2(a[m]);
#pragma unroll
        for (int p = 0; p < 4; p++) ffma2(acc2[m][p], am, b2[p]);
      }
    }
  }
  const int rr = r0 + ty * 8, cc2 = c0 + tx * 8;
#pragma unroll
  for (int m = 0; m < 8; m++) {
    ulonglong2 v0, v1;
    v0.x = acc2[m][0]; v0.y = acc2[m][1];
    v1.x = acc2[m][2]; v1.y = acc2[m][3];
    *(ulonglong2*)&g_G[(size_t)(rr + m) * NTOK + cc2]     = v0;
    *(ulonglong2*)&g_G[(size_t)(rr + m) * NTOK + cc2 + 4] = v1;
  }
}

// ---------------------------------------------------------------------------
// prep: D0[j][k] = slots_in[j] . t_k. Warp per column, slots cached in smem.
// ---------------------------------------------------------------------------
__global__ __launch_bounds__(512, 1) void prep_d0(
    const float* __restrict__ W, const float* __restrict__ slots_in) {
  extern __shared__ __align__(16) float sm[];
  const int tid = threadIdx.x, l = tid & 31, w = tid >> 5;
  {
    float4* d4 = (float4*)sm;
    const float4* s4 = (const float4*)slots_in;
    for (int k = tid; k < NSLOT * DIM / 4; k += 512) d4[k] = s4[k];
  }
  __syncthreads();
  const ulonglong2* sm2 = (const ulonglong2*)sm;
  const int k = blockIdx.x * 16 + w;
  const ulonglong2* xp = (const ulonglong2*)(W + (size_t)k * DIM);
  u64 xv[16];
#pragma unroll
  for (int q = 0; q < 8; q++) {
    ulonglong2 v = xp[l + 32 * q];
    xv[2 * q] = v.x; xv[2 * q + 1] = v.y;
  }
  float v[NSLOT];
#pragma unroll
  for (int j = 0; j < NSLOT; j++) {
    u64 p0 = 0, p1 = 0;
#pragma unroll
    for (int q = 0; q < 8; q++) {
      ulonglong2 sv = sm2[j * 256 + l + 32 * q];
      ffma2(p0, sv.x, xv[2 * q]); ffma2(p1, sv.y, xv[2 * q + 1]);
    }
    v[j] = hsum2(p0) + hsum2(p1);
  }
#pragma unroll
  for (int o = 16; o; o >>= 1) {
    bool hi = (l & o) != 0;
#pragma unroll
    for (int j = 0; j < o; j++) {
      float snd = hi ? v[j] : v[j + o];
      float rcv = __shfl_xor_sync(FULLM, snd, o);
      v[j] = (hi ? v[j + o] : v[j]) + rcv;
    }
  }
  g_D[l * NTOK + k] = v[0];
}

// ---------------------------------------------------------------------------
// Scan: 1 CTA x 768 threads. ROUTING WARP = 23 (highest wid -> wins the
// hi-wid-first arbiter on its SMSP; warps 3/7/11/15/19 can no longer starve
// the serial chain). Sweep/prefetch = warps 0..22. Logic otherwise R10-exact.
// ---------------------------------------------------------------------------
struct ScanSmem {
  float t2s[NTOK];
  float Dcol[2][BS][33];
  float Gdiag[2][BS][BS];
  float Gcross[BS][65];
  float pow95[BS + 1];
  float cvec[2][NSLOT];
  float swW[2][BS];
  float n2sh[NSLOT];
  int   sstart[2][NSLOT + 1];
  int   jlistS[2][BS];
  int   ordS[2][BS];
  int   mvec[2][NSLOT];
  int   swS[2][BS];
};

#define RW 23   // routing warp id

__global__ __launch_bounds__(768, 1) void scan_kernel(
    const float* __restrict__ slots_in, const float* __restrict__ usage_in) {
  extern __shared__ __align__(16) char smraw[];
  ScanSmem* S = (ScanSmem*)smraw;
  const int tid = threadIdx.x, w = tid >> 5, l = tid & 31;

  for (int t = tid; t < NTOK; t += 768) S->t2s[t] = g_G[(size_t)t * NTOK + t];
  for (int t = tid; t < NSLOT * BS; t += 768)
    S->Dcol[0][t & 63][t >> 6] = g_D[(t >> 6) * NTOK + (t & 63)];
  for (int t = tid; t < BS * BS; t += 768)
    S->Gdiag[0][t >> 6][t & 63] = g_G[(size_t)(t >> 6) * NTOK + (t & 63)];
  if (tid == 0) {
    float p = 1.f;
    for (int e = 0; e <= BS; e++) { S->pow95[e] = p; p *= 0.95f; }
  }
  for (int s = w; s < NSLOT; s += 24) {
    const float4* sp = (const float4*)(slots_in + (size_t)s * DIM);
    float a = 0.f;
#pragma unroll
    for (int q = 0; q < 8; q++) {
      float4 v = sp[l + 32 * q];
      a = fmaf(v.x, v.x, fmaf(v.y, v.y, fmaf(v.z, v.z, fmaf(v.w, v.w, a))));
    }
#pragma unroll
    for (int o = 16; o; o >>= 1) a += __shfl_xor_sync(FULLM, a, o);
    if (l == 0) S->n2sh[s] = a;
  }
  __syncthreads();

  float n2 = 0.f, usg = 0.f, rcp = 0.f;
  int nempty = 0;
  if (w == RW) {
    n2 = S->n2sh[l];
    usg = usage_in[l];
    rcp = rsqrtf(fmaxf(n2, 1e-16f));
    nempty = __popc(__ballot_sync(FULLM, usg == 0.f));
  }

  int cur = 0;
  for (int b = 0; b < NBLK; b++) {
    if (w == RW) {
      // ------- sequential routing, 64 steps, register current-row -------
      const int lb = b & 1;
      int mb = 0;
      float dn = S->Dcol[cur][0][l];
      for (int s = 0; s < BS; s++) {
        const int gi = b * BS + s;
        const int sn = (s < BS - 1) ? s + 1 : s;
        const float dnext = S->Dcol[cur][sn][l];
        const float gdn = S->Gdiag[cur][s][sn];
        const float n2c = 0.9025f * n2 + 0.095f * dn + 0.0025f * S->t2s[gi];
        const float rcpc = rsqrtf(fmaxf(n2c, 1e-16f));
        int j;
        if (nempty > 0) {
          unsigned em = __ballot_sync(FULLM, usg == 0.f);
          j = __ffs(em) - 1;
          nempty--;
        } else {
          float sim = dn * rcp;
          unsigned bk = __float_as_uint(sim);
          bk ^= (unsigned)((int)bk >> 31) | 0x80000000u;
          unsigned mk = __reduce_max_sync(FULLM, bk);
          j = __ffs(__ballot_sync(FULLM, bk == mk)) - 1;
        }
        const bool win = (l == j);
        if (win) {
          S->jlistS[lb][s] = j; S->ordS[lb][s] = mb;
          g_jl[gi] = j;
          n2 = n2c; rcp = rcpc;
          usg += 1.f; mb++;
        }
        dn = win ? fmaf(0.95f, dnext, 0.05f * gdn) : dnext;
        const int r1 = s + 2 + l;
        if (r1 < BS)
          S->Dcol[cur][r1][j] = fmaf(0.95f, S->Dcol[cur][r1][j], 0.05f * S->Gdiag[cur][s][r1]);
        const int r2 = s + 34 + l;
        if (r2 < BS)
          S->Dcol[cur][r2][j] = fmaf(0.95f, S->Dcol[cur][r2][j], 0.05f * S->Gdiag[cur][s][r2]);
      }
      S->mvec[lb][l] = mb;
      S->cvec[lb][l] = S->pow95[mb];
      int sc = mb;
#pragma unroll
      for (int o = 1; o < 32; o <<= 1) {
        int v = __shfl_up_sync(FULLM, sc, o);
        if (l >= o) sc += v;
      }
      S->sstart[lb][l] = sc - mb;
      if (l == 31) S->sstart[lb][32] = sc;
      __syncwarp();
      for (int s = l; s < BS; s += 32) {
        int j2 = S->jlistS[lb][s], od = S->ordS[lb][s];
        int pos = S->sstart[lb][j2] + od;
        S->swS[lb][pos] = s;
        S->swW[lb][pos] = 0.05f * S->pow95[S->mvec[lb][j2] - 1 - od];
      }
    } else {
      // ---- warps 0..22: slot-major sweep of block b-1's composite update ----
      const int wt = w * 32 + l;                // 0..735
      if (b > 0) {
        const int lb = (b - 1) & 1;
        const int j = wt & 31;
        const int g0 = wt >> 5;                 // 0..22
        const int colstart = (b + 1) * BS;
        const int ngrp = (NTOK - colstart) >> 2;
        const float c = S->cvec[lb][j];
        const int e0 = S->sstart[lb][j], e1 = S->sstart[lb][j + 1];
        float* const drow = &g_D[j * NTOK];
        int g = g0;
        for (; g + 23 < ngrp; g += 46) {
          const int kqA = colstart + g * 4;
          const int kqB = colstart + (g + 23) * 4;
          float4 dA = *(const float4*)&drow[kqA];
          float4 dB = *(const float4*)&drow[kqB];
          dA.x *= c; dA.y *= c; dA.z *= c; dA.w *= c;
          dB.x *= c; dB.y *= c; dB.z *= c; dB.w *= c;
#pragma unroll 1
          for (int e = e0; e < e1; e++) {
            const int gi = (b - 1) * BS + S->swS[lb][e];
            const float wgt = S->swW[lb][e];
            const float4 gA = *(const float4*)&g_G[(size_t)gi * NTOK + kqA];
            const float4 gB = *(const float4*)&g_G[(size_t)gi * NTOK + kqB];
            dA.x = fmaf(wgt, gA.x, dA.x); dA.y = fmaf(wgt, gA.y, dA.y);
            dA.z = fmaf(wgt, gA.z, dA.z); dA.w = fmaf(wgt, gA.w, dA.w);
            dB.x = fmaf(wgt, gB.x, dB.x); dB.y = fmaf(wgt, gB.y, dB.y);
            dB.z = fmaf(wgt, gB.z, dB.z); dB.w = fmaf(wgt, gB.w, dB.w);
          }
          *(float4*)&drow[kqA] = dA;
          *(float4*)&drow[kqB] = dB;
        }
        for (; g < ngrp; g += 23) {
          const int kq = colstart + g * 4;
          float4 dv = *(const float4*)&drow[kq];
          dv.x *= c; dv.y *= c; dv.z *= c; dv.w *= c;
#pragma unroll 1
          for (int e = e0; e < e1; e++) {
            const int gi = (b - 1) * BS + S->swS[lb][e];
            const float wgt = S->swW[lb][e];
            const float4 gv = *(const float4*)&g_G[(size_t)gi * NTOK + kq];
            dv.x = fmaf(wgt, gv.x, dv.x); dv.y = fmaf(wgt, gv.y, dv.y);
            dv.z = fmaf(wgt, gv.z, dv.z); dv.w = fmaf(wgt, gv.w, dv.w);
          }
          *(float4*)&drow[kq] = dv;
        }
      }
      asm volatile("bar.sync 1, 736;" ::: "memory");
      if (b + 1 < NBLK) {
        const int cb = (b + 1) * BS;
        const int nb2 = cur ^ 1;
        for (int t = wt; t < NSLOT * BS; t += 736)
          S->Dcol[nb2][t & 63][t >> 6] = g_D[(t >> 6) * NTOK + cb + (t & 63)];
        for (int t = wt; t < BS * BS; t += 736)
          S->Gdiag[nb2][t >> 6][t & 63] = g_G[(size_t)(cb + (t >> 6)) * NTOK + cb + (t & 63)];
        for (int t = wt; t < BS * BS; t += 736)
          S->Gcross[t & 63][t >> 6] = g_G[(size_t)(b * BS + (t >> 6)) * NTOK + cb + (t & 63)];
      }
    }
    __syncthreads();
    // ------- stage B: fold block-b update into the prefetched columns -------
    if (b + 1 < NBLK) {
      const int lb = b & 1;
      const int nb2 = cur ^ 1;
      for (int col = w; col < BS; col += 24) {
        float dvv = S->Dcol[nb2][col][l] * S->cvec[lb][l];
        const int e1 = S->sstart[lb][l + 1];
        for (int e = S->sstart[lb][l]; e < e1; e++)
          dvv = fmaf(S->swW[lb][e], S->Gcross[col][S->swS[lb][e]], dvv);
        S->Dcol[nb2][col][l] = dvv;
      }
    }
    __syncthreads();
    cur ^= 1;
  }
}

// ---------------------------------------------------------------------------
// Recon: prefix-scan per-slot event list, then depth-4 prefetched exact replay.
// ---------------------------------------------------------------------------
__global__ __launch_bounds__(1024, 1) void recon_kernel(
    const float* __restrict__ W, const float* __restrict__ slots_in) {
  __shared__ int jl[NTOK];
  __shared__ int ev[NTOK];
  __shared__ int wsum[32];
  __shared__ float red[32];
  __shared__ int ntot;
  const int j = blockIdx.x, tid = threadIdx.x, l = tid & 31, w = tid >> 5;
  for (int t = tid; t < NTOK; t += 1024) jl[t] = g_jl[t];
  __syncthreads();
  const int m0 = (jl[2 * tid] == j), m1 = (jl[2 * tid + 1] == j);
  const int cnt = m0 + m1;
  int sc = cnt;
#pragma unroll
  for (int o = 1; o < 32; o <<= 1) {
    int v = __shfl_up_sync(FULLM, sc, o);
    if (l >= o) sc += v;
  }
  if (l == 31) wsum[w] = sc;
  __syncthreads();
  if (w == 0) {
    int v = wsum[l];
#pragma unroll
    for (int o = 1; o < 32; o <<= 1) {
      int u = __shfl_up_sync(FULLM, v, o);
      if (l >= o) v += u;
    }
    wsum[l] = v;
    if (l == 31) ntot = v;
  }
  __syncthreads();
  const int base = (w ? wsum[w - 1] : 0) + sc - cnt;
  if (m0) ev[base] = 2 * tid;
  if (m1) ev[base + m0] = 2 * tid + 1;
  __syncthreads();

  const int n = ntot;
  float s = slots_in[(size_t)j * DIM + tid];
  float buf[4];
#pragma unroll
  for (int k = 0; k < 4; k++)
    buf[k] = (k < n) ? W[(size_t)ev[k] * DIM + tid] : 0.f;
  for (int k = 0; k < n; k++) {
    const float wc = buf[k & 3];
    const int kn = k + 4;
    buf[k & 3] = (kn < n) ? W[(size_t)ev[kn] * DIM + tid] : 0.f;
    s = 0.95f * s + 0.05f * wc;
  }
  g_slots[(size_t)j * DIM + tid] = s;
  float ss = s * s;
#pragma unroll
  for (int o = 16; o; o >>= 1) ss += __shfl_xor_sync(FULLM, ss, o);
  if (l == 0) red[w] = ss;
  __syncthreads();
  if (tid < 32) {
    float v = red[tid];
#pragma unroll
    for (int o = 16; o; o >>= 1) v += __shfl_xor_sync(FULLM, v, o);
    if (tid == 0) g_invn[j] = 1.f / fmaxf(sqrtf(fmaxf(v, 0.f)), 1e-12f);
  }
}

// ---------------------------------------------------------------------------
// Retrieve stage 1: scores + softmax -> g_w. 2 tokens/warp, pass-A only.
// ---------------------------------------------------------------------------
__global__ __launch_bounds__(256, 1) void retrieve_scores(
    const float* __restrict__ x) {
  extern __shared__ __align__(16) float sm[];
  __shared__ float invn_s[NSLOT];
  const int tid = threadIdx.x, l = tid & 31, w = tid >> 5;
  {
    float4* d4 = (float4*)sm;
    const float4* s4 = (const float4*)g_slots;
    for (int k = tid; k < NSLOT * DIM / 4; k += 256) d4[k] = s4[k];
    if (tid < NSLOT) invn_s[tid] = g_invn[tid];
  }
  __syncthreads();
  const ulonglong2* sm2 = (const ulonglong2*)sm;
  const int gw = blockIdx.x * 8 + w;
  const int nw = gridDim.x * 8;

  for (int p = gw; p < NQ / 2; p += nw) {
    const int t0 = 2 * p;
    const ulonglong2* xp0 = (const ulonglong2*)(x + (size_t)t0 * DIM);
    const ulonglong2* xp1 = (const ulonglong2*)(x + (size_t)(t0 + 1) * DIM);
    u64 xv0[16], xv1[16];
#pragma unroll
    for (int q = 0; q < 8; q++) {
      ulonglong2 v0 = xp0[l + 32 * q], v1 = xp1[l + 32 * q];
      xv0[2 * q] = v0.x; xv0[2 * q + 1] = v0.y;
      xv1[2 * q] = v1.x; xv1[2 * q + 1] = v1.y;
    }
    u64 a0 = 0, a1 = 0;
#pragma unroll
    for (int q = 0; q < 16; q++) { ffma2(a0, xv0[q], xv0[q]); ffma2(a1, xv1[q], xv1[q]); }
    float nx0 = hsum2(a0), nx1 = hsum2(a1);
#pragma unroll
    for (int o = 16; o; o >>= 1) {
      nx0 += __shfl_xor_sync(FULLM, nx0, o);
      nx1 += __shfl_xor_sync(FULLM, nx1, o);
    }
    const float rx0 = 1.f / fmaxf(sqrtf(nx0), 1e-12f);
    const float rx1 = 1.f / fmaxf(sqrtf(nx1), 1e-12f);

    float v0[NSLOT], v1[NSLOT];
#pragma unroll
    for (int j = 0; j < NSLOT; j++) {
      u64 p00 = 0, p01 = 0, p10 = 0, p11 = 0;
#pragma unroll
      for (int q = 0; q < 8; q++) {
        ulonglong2 sv = sm2[j * 256 + l + 32 * q];
        ffma2(p00, sv.x, xv0[2 * q]); ffma2(p01, sv.y, xv0[2 * q + 1]);
        ffma2(p10, sv.x, xv1[2 * q]); ffma2(p11, sv.y, xv1[2 * q + 1]);
      }
      v0[j] = hsum2(p00) + hsum2(p01);
      v1[j] = hsum2(p10) + hsum2(p11);
    }
#pragma unroll
    for (int o = 16; o; o >>= 1) {
      const bool hi = (l & o) != 0;
#pragma unroll
      for (int j = 0; j < o; j++) {
        float s0 = hi ? v0[j] : v0[j + o];
        float r0 = __shfl_xor_sync(FULLM, s0, o);
        v0[j] = (hi ? v0[j + o] : v0[j]) + r0;
        float s1 = hi ? v1[j] : v1[j + o];
        float r1 = __shfl_xor_sync(FULLM, s1, o);
        v1[j] = (hi ? v1[j + o] : v1[j]) + r1;
      }
    }
    const float in_l = invn_s[l];
    float sc0 = v0[0] * in_l * rx0 * INV_TEMP;
    float sc1 = v1[0] * in_l * rx1 * INV_TEMP;
    float m0 = sc0, m1 = sc1;
#pragma unroll
    for (int o = 16; o; o >>= 1) {
      m0 = fmaxf(m0, __shfl_xor_sync(FULLM, m0, o));
      m1 = fmaxf(m1, __shfl_xor_sync(FULLM, m1, o));
    }
    const float e0 = __expf(sc0 - m0), e1 = __expf(sc1 - m1);
    float se0 = e0, se1 = e1;
#pragma unroll
    for (int o = 16; o; o >>= 1) {
      se0 += __shfl_xor_sync(FULLM, se0, o);
      se1 += __shfl_xor_sync(FULLM, se1, o);
    }
    g_w[(size_t)t0 * NSLOT + l]       = e0 * (1.f / se0);
    g_w[(size_t)(t0 + 1) * NSLOT + l] = e1 * (1.f / se1);
  }
}

// ---------------------------------------------------------------------------
// Retrieve stage 2: out = w @ slots. Warp = 4 tokens x half the dims.
// ---------------------------------------------------------------------------
__global__ __launch_bounds__(256, 1) void retrieve_out(float* __restrict__ out) {
  extern __shared__ __align__(16) float sm[];
  const int tid = threadIdx.x, l = tid & 31, w = tid >> 5;
  {
    float4* d4 = (float4*)sm;
    const float4* s4 = (const float4*)g_slots;
    for (int k = tid; k < NSLOT * DIM / 4; k += 256) d4[k] = s4[k];
  }
  __syncthreads();
  const ulonglong2* sm2 = (const ulonglong2*)sm;
  const int gw = blockIdx.x * 8 + w;
  const int nw = gridDim.x * 8;
  const int nitems = (NQ / 4) * 2;

  for (int it = gw; it < nitems; it += nw) {
    const int t0 = (it >> 1) * 4;
    const int h = it & 1;
    float wreg[4];
#pragma unroll
    for (int t = 0; t < 4; t++) wreg[t] = g_w[(size_t)(t0 + t) * NSLOT + l];

    u64 acc[4][8];
#pragma unroll
    for (int t = 0; t < 4; t++)
#pragma unroll
      for (int k = 0; k < 8; k++) acc[t][k] = 0;

#pragma unroll 4
    for (int j = 0; j < NSLOT; j++) {
      ulonglong2 sv[4];
#pragma unroll
      for (int k = 0; k < 4; k++) sv[k] = sm2[j * 256 + h * 128 + l + 32 * k];
      u64 wj[4];
#pragma unroll
      for (int t = 0; t < 4; t++) wj[t] = pack2(__shfl_sync(FULLM, wreg[t], j));
#pragma unroll
      for (int t = 0; t < 4; t++)
#pragma unroll
        for (int k = 0; k < 4; k++) {
          ffma2(acc[t][2 * k],     sv[k].x, wj[t]);
          ffma2(acc[t][2 * k + 1], sv[k].y, wj[t]);
        }
    }
    ulonglong2* op = (ulonglong2*)out;
#pragma unroll
    for (int t = 0; t < 4; t++)
#pragma unroll
      for (int k = 0; k < 4; k++) {
        ulonglong2 ov; ov.x = acc[t][2 * k]; ov.y = acc[t][2 * k + 1];
        op[(size_t)(t0 + t) * 256 + h * 128 + l + 32 * k] = ov;
      }
  }
}

extern "C" void kernel_launch(void* const* d_in, const int* in_sizes, int n_in,
                              void* d_out, int out_size) {
  const float* x     = (const float*)d_in[0];
  const float* W     = (const float*)d_in[1];
  const float* slots = (const float*)d_in[2];
  const float* usage = (const float*)d_in[3];
  float* out = (float*)d_out;

  const int slot_smem = NSLOT * DIM * (int)sizeof(float);
  cudaFuncSetAttribute(retrieve_scores, cudaFuncAttributeMaxDynamicSharedMemorySize, slot_smem);
  cudaFuncSetAttribute(retrieve_out, cudaFuncAttributeMaxDynamicSharedMemorySize, slot_smem);
  cudaFuncSetAttribute(prep_d0, cudaFuncAttributeMaxDynamicSharedMemorySize, slot_smem);
  cudaFuncSetAttribute(scan_kernel, cudaFuncAttributeMaxDynamicSharedMemorySize,
                       (int)sizeof(ScanSmem));

  gram_kernel<<<136, 256>>>(W);
  prep_d0<<<NTOK / 16, 512, slot_smem>>>(W, slots);
  scan_kernel<<<1, 768, sizeof(ScanSmem)>>>(slots, usage);
  recon_kernel<<<NSLOT, 1024>>>(W, slots);
  retrieve_scores<<<148, 256, slot_smem>>>(x);
  retrieve_out<<<148, 256, slot_smem>>>(out);
}

// round 16
// speedup vs baseline: 1.0754x; 1.0454x over previous
#include <cuda_runtime.h>
#include <cstdint>

#define DIM   1024
#define NSLOT 32
#define NTOK  2048
#define NQ    32768
#define BS    64
#define NBLK  32
#define FULLM 0xffffffffu
#define INV_TEMP (1.0f/0.35f)

typedef unsigned long long u64;

// ---- device scratch ----
__device__ __align__(16) float g_G[NTOK * (size_t)NTOK];   // Gram, upper triangle valid
__device__ __align__(16) float g_D[NSLOT * NTOK];          // slot-token dots
__device__ int   g_jl[NTOK];
__device__ __align__(16) float g_slots[NSLOT * DIM];
__device__ float g_invn[NSLOT];
__device__ __align__(16) float g_w[NQ * NSLOT];            // softmax weights

// ---- packed f32x2 helpers ----
__device__ __forceinline__ void ffma2(u64 &d, u64 a, u64 b) {
  asm("fma.rn.f32x2 %0, %1, %2, %0;" : "+l"(d) : "l"(a), "l"(b));
}
__device__ __forceinline__ u64 mul2(u64 a, u64 b) {
  u64 d; asm("mul.rn.f32x2 %0, %1, %2;" : "=l"(d) : "l"(a), "l"(b)); return d;
}
__device__ __forceinline__ u64 pack2(float x) {
  u64 d; asm("mov.b64 %0, {%1, %1};" : "=l"(d) : "f"(x)); return d;
}
__device__ __forceinline__ float hsum2(u64 u) {
  float lo, hi; asm("mov.b64 {%0, %1}, %2;" : "=f"(lo), "=f"(hi) : "l"(u));
  return lo + hi;
}

// ---------------------------------------------------------------------------
// Gram GEMM: triangular tile grid (136 CTAs), FFMA2 microkernel (R10 exact).
// ---------------------------------------------------------------------------
__global__ __launch_bounds__(256, 2) void gram_kernel(const float* __restrict__ W) {
  int ttile = blockIdx.x, bx = 0;
  while (ttile >= 16 - bx) { ttile -= 16 - bx; bx++; }
  const int by = bx + ttile;

  __shared__ float As[16][132];
  __shared__ float Bs[16][132];
  const int tid = threadIdx.x;
  const int tx = tid & 15, ty = tid >> 4;
  u64 acc2[8][4];
#pragma unroll
  for (int m = 0; m < 8; m++)
#pragma unroll
    for (int p = 0; p < 4; p++) acc2[m][p] = 0ull;
  const int r0 = bx * 128, c0 = by * 128;
  const int lr = tid >> 2, kq = (tid & 3) << 2;

  for (int k0 = 0; k0 < DIM; k0 += 16) {
    float4 a0 = *(const float4*)&W[(size_t)(r0 + lr) * DIM + k0 + kq];
    float4 a1 = *(const float4*)&W[(size_t)(r0 + lr + 64) * DIM + k0 + kq];
    float4 b0 = *(const float4*)&W[(size_t)(c0 + lr) * DIM + k0 + kq];
    float4 b1 = *(const float4*)&W[(size_t)(c0 + lr + 64) * DIM + k0 + kq];
    __syncthreads();
    As[kq + 0][lr] = a0.x; As[kq + 1][lr] = a0.y; As[kq + 2][lr] = a0.z; As[kq + 3][lr] = a0.w;
    As[kq + 0][lr + 64] = a1.x; As[kq + 1][lr + 64] = a1.y; As[kq + 2][lr + 64] = a1.z; As[kq + 3][lr + 64] = a1.w;
    Bs[kq + 0][lr] = b0.x; Bs[kq + 1][lr] = b0.y; Bs[kq + 2][lr] = b0.z; Bs[kq + 3][lr] = b0.w;
    Bs[kq + 0][lr + 64] = b1.x; Bs[kq + 1][lr + 64] = b1.y; Bs[kq + 2][lr + 64] = b1.z; Bs[kq + 3][lr + 64] = b1.w;
    __syncthreads();
#pragma unroll
    for (int kk = 0; kk < 16; kk++) {
      float a[8];
      *(float4*)a       = *(const float4*)&As[kk][ty * 8];
      *(float4*)(a + 4) = *(const float4*)&As[kk][ty * 8 + 4];
      u64 b2[4];
      *(ulonglong2*)&b2[0] = *(const ulonglong2*)&Bs[kk][tx * 8];
      *(ulonglong2*)&b2[2] = *(const ulonglong2*)&Bs[kk][tx * 8 + 4];
#pragma unroll
      for (int m = 0; m < 8; m++) {
        const u64 am = pack2(a[m]);
#pragma unroll
        for (int p = 0; p < 4; p++) ffma2(acc2[m][p], am, b2[p]);
      }
    }
  }
  const int rr = r0 + ty * 8, cc2 = c0 + tx * 8;
#pragma unroll
  for (int m = 0; m < 8; m++) {
    ulonglong2 v0, v1;
    v0.x = acc2[m][0]; v0.y = acc2[m][1];
    v1.x = acc2[m][2]; v1.y = acc2[m][3];
    *(ulonglong2*)&g_G[(size_t)(rr + m) * NTOK + cc2]     = v0;
    *(ulonglong2*)&g_G[(size_t)(rr + m) * NTOK + cc2 + 4] = v1;
  }
}

// ---------------------------------------------------------------------------
// prep: D0[j][k] = slots_in[j] . t_k. Warp per column, slots cached in smem.
// ---------------------------------------------------------------------------
__global__ __launch_bounds__(512, 1) void prep_d0(
    const float* __restrict__ W, const float* __restrict__ slots_in) {
  extern __shared__ __align__(16) float sm[];
  const int tid = threadIdx.x, l = tid & 31, w = tid >> 5;
  {
    float4* d4 = (float4*)sm;
    const float4* s4 = (const float4*)slots_in;
    for (int k = tid; k < NSLOT * DIM / 4; k += 512) d4[k] = s4[k];
  }
  __syncthreads();
  const ulonglong2* sm2 = (const ulonglong2*)sm;
  const int k = blockIdx.x * 16 + w;
  const ulonglong2* xp = (const ulonglong2*)(W + (size_t)k * DIM);
  u64 xv[16];
#pragma unroll
  for (int q = 0; q < 8; q++) {
    ulonglong2 v = xp[l + 32 * q];
    xv[2 * q] = v.x; xv[2 * q + 1] = v.y;
  }
  float v[NSLOT];
#pragma unroll
  for (int j = 0; j < NSLOT; j++) {
    u64 p0 = 0, p1 = 0;
#pragma unroll
    for (int q = 0; q < 8; q++) {
      ulonglong2 sv = sm2[j * 256 + l + 32 * q];
      ffma2(p0, sv.x, xv[2 * q]); ffma2(p1, sv.y, xv[2 * q + 1]);
    }
    v[j] = hsum2(p0) + hsum2(p1);
  }
#pragma unroll
  for (int o = 16; o; o >>= 1) {
    bool hi = (l & o) != 0;
#pragma unroll
    for (int j = 0; j < o; j++) {
      float snd = hi ? v[j] : v[j + o];
      float rcv = __shfl_xor_sync(FULLM, snd, o);
      v[j] = (hi ? v[j + o] : v[j]) + rcv;
    }
  }
  g_D[l * NTOK + k] = v[0];
}

// ---------------------------------------------------------------------------
// Scan: 1 CTA x 768 threads. Routing warp 23, BRANCH-FREE inner step:
// both routing paths computed every step, SEL-committed; all conditional
// state updates are single-statement predicated ops (no BSSY/BSYNC in loop).
// ---------------------------------------------------------------------------
struct ScanSmem {
  float t2s[NTOK];
  float Dcol[2][BS][33];
  float Gdiag[2][BS][BS];
  float Gcross[BS][65];
  float pow95[BS + 1];
  float cvec[2][NSLOT];
  float swW[2][BS];
  float n2sh[NSLOT];
  int   sstart[2][NSLOT + 1];
  int   jlistS[2][BS];
  int   ordS[2][BS];
  int   mvec[2][NSLOT];
  int   swS[2][BS];
};

#define RW 23   // routing warp id

__global__ __launch_bounds__(768, 1) void scan_kernel(
    const float* __restrict__ slots_in, const float* __restrict__ usage_in) {
  extern __shared__ __align__(16) char smraw[];
  ScanSmem* S = (ScanSmem*)smraw;
  const int tid = threadIdx.x, w = tid >> 5, l = tid & 31;

  for (int t = tid; t < NTOK; t += 768) S->t2s[t] = g_G[(size_t)t * NTOK + t];
  for (int t = tid; t < NSLOT * BS; t += 768)
    S->Dcol[0][t & 63][t >> 6] = g_D[(t >> 6) * NTOK + (t & 63)];
  for (int t = tid; t < BS * BS; t += 768)
    S->Gdiag[0][t >> 6][t & 63] = g_G[(size_t)(t >> 6) * NTOK + (t & 63)];
  if (tid == 0) {
    float p = 1.f;
    for (int e = 0; e <= BS; e++) { S->pow95[e] = p; p *= 0.95f; }
  }
  for (int s = w; s < NSLOT; s += 24) {
    const float4* sp = (const float4*)(slots_in + (size_t)s * DIM);
    float a = 0.f;
#pragma unroll
    for (int q = 0; q < 8; q++) {
      float4 v = sp[l + 32 * q];
      a = fmaf(v.x, v.x, fmaf(v.y, v.y, fmaf(v.z, v.z, fmaf(v.w, v.w, a))));
    }
#pragma unroll
    for (int o = 16; o; o >>= 1) a += __shfl_xor_sync(FULLM, a, o);
    if (l == 0) S->n2sh[s] = a;
  }
  __syncthreads();

  float n2 = 0.f, usg = 0.f, rcp = 0.f;
  if (w == RW) {
    n2 = S->n2sh[l];
    usg = usage_in[l];
    rcp = rsqrtf(fmaxf(n2, 1e-16f));
  }

  int cur = 0;
  for (int b = 0; b < NBLK; b++) {
    if (w == RW) {
      // ------- sequential routing, 64 steps, branch-free body -------
      const int lb = b & 1;
      int mb = 0;
      float dn = S->Dcol[cur][0][l];
#pragma unroll 4
      for (int s = 0; s < BS; s++) {
        const int gi = b * BS + s;
        const int sn = (s < BS - 1) ? s + 1 : s;
        const float dnext = S->Dcol[cur][sn][l];
        const float gdn = S->Gdiag[cur][s][sn];
        // speculative n2'/rcp' for every lane (off critical path)
        const float n2c = 0.9025f * n2 + 0.095f * dn + 0.0025f * S->t2s[gi];
        const float rcpc = rsqrtf(fmaxf(n2c, 1e-16f));
        // empty path (2 cheap warp ops, computed always)
        const unsigned em = __ballot_sync(FULLM, usg == 0.f);
        // argmax path (computed always)
        const float sim = dn * rcp;
        unsigned bk = __float_as_uint(sim);
        bk ^= (unsigned)((int)bk >> 31) | 0x80000000u;
        const unsigned mk = __reduce_max_sync(FULLM, bk);
        const unsigned bal = __ballot_sync(FULLM, bk == mk);
        const int jmax = __ffs(bal) - 1;
        const int jemp = __ffs(em) - 1;
        const int j = (em != 0u) ? jemp : jmax;     // SEL (uniform)
        const bool win = (l == j);
        // single-statement predicated commits (no BSSY)
        if (win) S->jlistS[lb][s] = j;
        if (win) S->ordS[lb][s] = mb;
        if (win) g_jl[gi] = j;
        n2  = win ? n2c : n2;
        rcp = win ? rcpc : rcp;
        usg = win ? (usg + 1.f) : usg;
        mb += (int)win;
        dn  = win ? fmaf(0.95f, dnext, 0.05f * gdn) : dnext;
        // future-row updates (consumers >= 1 full step away), predicated
        const int r1 = s + 2 + l;
        const int r2 = s + 34 + l;
        if (r1 < BS)
          S->Dcol[cur][r1][j] = fmaf(0.95f, S->Dcol[cur][r1][j], 0.05f * S->Gdiag[cur][s][r1]);
        if (r2 < BS)
          S->Dcol[cur][r2][j] = fmaf(0.95f, S->Dcol[cur][r2][j], 0.05f * S->Gdiag[cur][s][r2]);
      }
      S->mvec[lb][l] = mb;
      S->cvec[lb][l] = S->pow95[mb];
      int sc = mb;
#pragma unroll
      for (int o = 1; o < 32; o <<= 1) {
        int v = __shfl_up_sync(FULLM, sc, o);
        if (l >= o) sc += v;
      }
      S->sstart[lb][l] = sc - mb;
      if (l == 31) S->sstart[lb][32] = sc;
      __syncwarp();
      for (int s = l; s < BS; s += 32) {
        int j2 = S->jlistS[lb][s], od = S->ordS[lb][s];
        int pos = S->sstart[lb][j2] + od;
        S->swS[lb][pos] = s;
        S->swW[lb][pos] = 0.05f * S->pow95[S->mvec[lb][j2] - 1 - od];
      }
    } else {
      // ---- warps 0..22: slot-major sweep of block b-1's composite update ----
      const int wt = w * 32 + l;                // 0..735
      if (b > 0) {
        const int lb = (b - 1) & 1;
        const int j = wt & 31;
        const int g0 = wt >> 5;                 // 0..22
        const int colstart = (b + 1) * BS;
        const int ngrp = (NTOK - colstart) >> 2;
        const float c = S->cvec[lb][j];
        const int e0 = S->sstart[lb][j], e1 = S->sstart[lb][j + 1];
        float* const drow = &g_D[j * NTOK];
        int g = g0;
        for (; g + 23 < ngrp; g += 46) {
          const int kqA = colstart + g * 4;
          const int kqB = colstart + (g + 23) * 4;
          float4 dA = *(const float4*)&drow[kqA];
          float4 dB = *(const float4*)&drow[kqB];
          dA.x *= c; dA.y *= c; dA.z *= c; dA.w *= c;
          dB.x *= c; dB.y *= c; dB.z *= c; dB.w *= c;
#pragma unroll 1
          for (int e = e0; e < e1; e++) {
            const int gi = (b - 1) * BS + S->swS[lb][e];
            const float wgt = S->swW[lb][e];
            const float4 gA = *(const float4*)&g_G[(size_t)gi * NTOK + kqA];
            const float4 gB = *(const float4*)&g_G[(size_t)gi * NTOK + kqB];
            dA.x = fmaf(wgt, gA.x, dA.x); dA.y = fmaf(wgt, gA.y, dA.y);
            dA.z = fmaf(wgt, gA.z, dA.z); dA.w = fmaf(wgt, gA.w, dA.w);
            dB.x = fmaf(wgt, gB.x, dB.x); dB.y = fmaf(wgt, gB.y, dB.y);
            dB.z = fmaf(wgt, gB.z, dB.z); dB.w = fmaf(wgt, gB.w, dB.w);
          }
          *(float4*)&drow[kqA] = dA;
          *(float4*)&drow[kqB] = dB;
        }
        for (; g < ngrp; g += 23) {
          const int kq = colstart + g * 4;
          float4 dv = *(const float4*)&drow[kq];
          dv.x *= c; dv.y *= c; dv.z *= c; dv.w *= c;
#pragma unroll 1
          for (int e = e0; e < e1; e++) {
            const int gi = (b - 1) * BS + S->swS[lb][e];
            const float wgt = S->swW[lb][e];
            const float4 gv = *(const float4*)&g_G[(size_t)gi * NTOK + kq];
            dv.x = fmaf(wgt, gv.x, dv.x); dv.y = fmaf(wgt, gv.y, dv.y);
            dv.z = fmaf(wgt, gv.z, dv.z); dv.w = fmaf(wgt, gv.w, dv.w);
          }
          *(float4*)&drow[kq] = dv;
        }
      }
      asm volatile("bar.sync 1, 736;" ::: "memory");
      if (b + 1 < NBLK) {
        const int cb = (b + 1) * BS;
        const int nb2 = cur ^ 1;
        for (int t = wt; t < NSLOT * BS; t += 736)
          S->Dcol[nb2][t & 63][t >> 6] = g_D[(t >> 6) * NTOK + cb + (t & 63)];
        for (int t = wt; t < BS * BS; t += 736)
          S->Gdiag[nb2][t >> 6][t & 63] = g_G[(size_t)(cb + (t >> 6)) * NTOK + cb + (t & 63)];
        for (int t = wt; t < BS * BS; t += 736)
          S->Gcross[t & 63][t >> 6] = g_G[(size_t)(b * BS + (t >> 6)) * NTOK + cb + (t & 63)];
      }
    }
    __syncthreads();
    // ------- stage B: fold block-b update into the prefetched columns -------
    if (b + 1 < NBLK) {
      const int lb = b & 1;
      const int nb2 = cur ^ 1;
      for (int col = w; col < BS; col += 24) {
        float dvv = S->Dcol[nb2][col][l] * S->cvec[lb][l];
        const int e1 = S->sstart[lb][l + 1];
        for (int e = S->sstart[lb][l]; e < e1; e++)
          dvv = fmaf(S->swW[lb][e], S->Gcross[col][S->swS[lb][e]], dvv);
        S->Dcol[nb2][col][l] = dvv;
      }
    }
    __syncthreads();
    cur ^= 1;
  }
}

// ---------------------------------------------------------------------------
// Recon: prefix-scan per-slot event list, then depth-4 prefetched exact replay.
// ---------------------------------------------------------------------------
__global__ __launch_bounds__(1024, 1) void recon_kernel(
    const float* __restrict__ W, const float* __restrict__ slots_in) {
  __shared__ int jl[NTOK];
  __shared__ int ev[NTOK];
  __shared__ int wsum[32];
  __shared__ float red[32];
  __shared__ int ntot;
  const int j = blockIdx.x, tid = threadIdx.x, l = tid & 31, w = tid >> 5;
  for (int t = tid; t < NTOK; t += 1024) jl[t] = g_jl[t];
  __syncthreads();
  const int m0 = (jl[2 * tid] == j), m1 = (jl[2 * tid + 1] == j);
  const int cnt = m0 + m1;
  int sc = cnt;
#pragma unroll
  for (int o = 1; o < 32; o <<= 1) {
    int v = __shfl_up_sync(FULLM, sc, o);
    if (l >= o) sc += v;
  }
  if (l == 31) wsum[w] = sc;
  __syncthreads();
  if (w == 0) {
    int v = wsum[l];
#pragma unroll
    for (int o = 1; o < 32; o <<= 1) {
      int u = __shfl_up_sync(FULLM, v, o);
      if (l >= o) v += u;
    }
    wsum[l] = v;
    if (l == 31) ntot = v;
  }
  __syncthreads();
  const int base = (w ? wsum[w - 1] : 0) + sc - cnt;
  if (m0) ev[base] = 2 * tid;
  if (m1) ev[base + m0] = 2 * tid + 1;
  __syncthreads();

  const int n = ntot;
  float s = slots_in[(size_t)j * DIM + tid];
  float buf[4];
#pragma unroll
  for (int k = 0; k < 4; k++)
    buf[k] = (k < n) ? W[(size_t)ev[k] * DIM + tid] : 0.f;
  for (int k = 0; k < n; k++) {
    const float wc = buf[k & 3];
    const int kn = k + 4;
    buf[k & 3] = (kn < n) ? W[(size_t)ev[kn] * DIM + tid] : 0.f;
    s = 0.95f * s + 0.05f * wc;
  }
  g_slots[(size_t)j * DIM + tid] = s;
  float ss = s * s;
#pragma unroll
  for (int o = 16; o; o >>= 1) ss += __shfl_xor_sync(FULLM, ss, o);
  if (l == 0) red[w] = ss;
  __syncthreads();
  if (tid < 32) {
    float v = red[tid];
#pragma unroll
    for (int o = 16; o; o >>= 1) v += __shfl_xor_sync(FULLM, v, o);
    if (tid == 0) g_invn[j] = 1.f / fmaxf(sqrtf(fmaxf(v, 0.f)), 1e-12f);
  }
}

// ---------------------------------------------------------------------------
// Retrieve stage 1: scores + softmax -> g_w. 2 tokens/warp, pass-A only.
// ---------------------------------------------------------------------------
__global__ __launch_bounds__(256, 1) void retrieve_scores(
    const float* __restrict__ x) {
  extern __shared__ __align__(16) float sm[];
  __shared__ float invn_s[NSLOT];
  const int tid = threadIdx.x, l = tid & 31, w = tid >> 5;
  {
    float4* d4 = (float4*)sm;
    const float4* s4 = (const float4*)g_slots;
    for (int k = tid; k < NSLOT * DIM / 4; k += 256) d4[k] = s4[k];
    if (tid < NSLOT) invn_s[tid] = g_invn[tid];
  }
  __syncthreads();
  const ulonglong2* sm2 = (const ulonglong2*)sm;
  const int gw = blockIdx.x * 8 + w;
  const int nw = gridDim.x * 8;

  for (int p = gw; p < NQ / 2; p += nw) {
    const int t0 = 2 * p;
    const ulonglong2* xp0 = (const ulonglong2*)(x + (size_t)t0 * DIM);
    const ulonglong2* xp1 = (const ulonglong2*)(x + (size_t)(t0 + 1) * DIM);
    u64 xv0[16], xv1[16];
#pragma unroll
    for (int q = 0; q < 8; q++) {
      ulonglong2 v0 = xp0[l + 32 * q], v1 = xp1[l + 32 * q];
      xv0[2 * q] = v0.x; xv0[2 * q + 1] = v0.y;
      xv1[2 * q] = v1.x; xv1[2 * q + 1] = v1.y;
    }
    u64 a0 = 0, a1 = 0;
#pragma unroll
    for (int q = 0; q < 16; q++) { ffma2(a0, xv0[q], xv0[q]); ffma2(a1, xv1[q], xv1[q]); }
    float nx0 = hsum2(a0), nx1 = hsum2(a1);
#pragma unroll
    for (int o = 16; o; o >>= 1) {
      nx0 += __shfl_xor_sync(FULLM, nx0, o);
      nx1 += __shfl_xor_sync(FULLM, nx1, o);
    }
    const float rx0 = 1.f / fmaxf(sqrtf(nx0), 1e-12f);
    const float rx1 = 1.f / fmaxf(sqrtf(nx1), 1e-12f);

    float v0[NSLOT], v1[NSLOT];
#pragma unroll
    for (int j = 0; j < NSLOT; j++) {
      u64 p00 = 0, p01 = 0, p10 = 0, p11 = 0;
#pragma unroll
      for (int q = 0; q < 8; q++) {
        ulonglong2 sv = sm2[j * 256 + l + 32 * q];
        ffma2(p00, sv.x, xv0[2 * q]); ffma2(p01, sv.y, xv0[2 * q + 1]);
        ffma2(p10, sv.x, xv1[2 * q]); ffma2(p11, sv.y, xv1[2 * q + 1]);
      }
      v0[j] = hsum2(p00) + hsum2(p01);
      v1[j] = hsum2(p10) + hsum2(p11);
    }
#pragma unroll
    for (int o = 16; o; o >>= 1) {
      const bool hi = (l & o) != 0;
#pragma unroll
      for (int j = 0; j < o; j++) {
        float s0 = hi ? v0[j] : v0[j + o];
        float r0 = __shfl_xor_sync(FULLM, s0, o);
        v0[j] = (hi ? v0[j + o] : v0[j]) + r0;
        float s1 = hi ? v1[j] : v1[j + o];
        float r1 = __shfl_xor_sync(FULLM, s1, o);
        v1[j] = (hi ? v1[j + o] : v1[j]) + r1;
      }
    }
    const float in_l = invn_s[l];
    float sc0 = v0[0] * in_l * rx0 * INV_TEMP;
    float sc1 = v1[0] * in_l * rx1 * INV_TEMP;
    float m0 = sc0, m1 = sc1;
#pragma unroll
    for (int o = 16; o; o >>= 1) {
      m0 = fmaxf(m0, __shfl_xor_sync(FULLM, m0, o));
      m1 = fmaxf(m1, __shfl_xor_sync(FULLM, m1, o));
    }
    const float e0 = __expf(sc0 - m0), e1 = __expf(sc1 - m1);
    float se0 = e0, se1 = e1;
#pragma unroll
    for (int o = 16; o; o >>= 1) {
      se0 += __shfl_xor_sync(FULLM, se0, o);
      se1 += __shfl_xor_sync(FULLM, se1, o);
    }
    g_w[(size_t)t0 * NSLOT + l]       = e0 * (1.f / se0);
    g_w[(size_t)(t0 + 1) * NSLOT + l] = e1 * (1.f / se1);
  }
}

// ---------------------------------------------------------------------------
// Retrieve stage 2: out = w @ slots. Warp = 4 tokens x half the dims.
// ---------------------------------------------------------------------------
__global__ __launch_bounds__(256, 1) void retrieve_out(float* __restrict__ out) {
  extern __shared__ __align__(16) float sm[];
  const int tid = threadIdx.x, l = tid & 31, w = tid >> 5;
  {
    float4* d4 = (float4*)sm;
    const float4* s4 = (const float4*)g_slots;
    for (int k = tid; k < NSLOT * DIM / 4; k += 256) d4[k] = s4[k];
  }
  __syncthreads();
  const ulonglong2* sm2 = (const ulonglong2*)sm;
  const int gw = blockIdx.x * 8 + w;
  const int nw = gridDim.x * 8;
  const int nitems = (NQ / 4) * 2;

  for (int it = gw; it < nitems; it += nw) {
    const int t0 = (it >> 1) * 4;
    const int h = it & 1;
    float wreg[4];
#pragma unroll
    for (int t = 0; t < 4; t++) wreg[t] = g_w[(size_t)(t0 + t) * NSLOT + l];

    u64 acc[4][8];
#pragma unroll
    for (int t = 0; t < 4; t++)
#pragma unroll
      for (int k = 0; k < 8; k++) acc[t][k] = 0;

#pragma unroll 4
    for (int j = 0; j < NSLOT; j++) {
      ulonglong2 sv[4];
#pragma unroll
      for (int k = 0; k < 4; k++) sv[k] = sm2[j * 256 + h * 128 + l + 32 * k];
      u64 wj[4];
#pragma unroll
      for (int t = 0; t < 4; t++) wj[t] = pack2(__shfl_sync(FULLM, wreg[t], j));
#pragma unroll
      for (int t = 0; t < 4; t++)
#pragma unroll
        for (int k = 0; k < 4; k++) {
          ffma2(acc[t][2 * k],     sv[k].x, wj[t]);
          ffma2(acc[t][2 * k + 1], sv[k].y, wj[t]);
        }
    }
    ulonglong2* op = (ulonglong2*)out;
#pragma unroll
    for (int t = 0; t < 4; t++)
#pragma unroll
      for (int k = 0; k < 4; k++) {
        ulonglong2 ov; ov.x = acc[t][2 * k]; ov.y = acc[t][2 * k + 1];
        op[(size_t)(t0 + t) * 256 + h * 128 + l + 32 * k] = ov;
      }
  }
}

extern "C" void kernel_launch(void* const* d_in, const int* in_sizes, int n_in,
                              void* d_out, int out_size) {
  const float* x     = (const float*)d_in[0];
  const float* W     = (const float*)d_in[1];
  const float* slots = (const float*)d_in[2];
  const float* usage = (const float*)d_in[3];
  float* out = (float*)d_out;

  const int slot_smem = NSLOT * DIM * (int)sizeof(float);
  cudaFuncSetAttribute(retrieve_scores, cudaFuncAttributeMaxDynamicSharedMemorySize, slot_smem);
  cudaFuncSetAttribute(retrieve_out, cudaFuncAttributeMaxDynamicSharedMemorySize, slot_smem);
  cudaFuncSetAttribute(prep_d0, cudaFuncAttributeMaxDynamicSharedMemorySize, slot_smem);
  cudaFuncSetAttribute(scan_kernel, cudaFuncAttributeMaxDynamicSharedMemorySize,
                       (int)sizeof(ScanSmem));

  gram_kernel<<<136, 256>>>(W);
  prep_d0<<<NTOK / 16, 512, slot_smem>>>(W, slots);
  scan_kernel<<<1, 768, sizeof(ScanSmem)>>>(slots, usage);
  recon_kernel<<<NSLOT, 1024>>>(W, slots);
  retrieve_scores<<<148, 256, slot_smem>>>(x);
  retrieve_out<<<148, 256, slot_smem>>>(out);
}